// round 1
// baseline (speedup 1.0000x reference)
#include <cuda_runtime.h>
#include <cuda_bf16.h>
#include <cstdint>

#define NODES 100000
#define EDGES 1600000
#define D 32
#define LAYERS 3
#define HOPS 3

// ---------------- scratch (device globals; no allocation allowed) ----------------
__device__ float g_norm[EDGES];
__device__ float g_deg[NODES];        // deg, then overwritten in-place with deg^{-1/2}
__device__ float g_h1[NODES * D];
__device__ float g_h2[NODES * D];
__device__ float g_out[NODES * D];
__device__ float g_x[NODES * D];

// ---------------- kernels ----------------

// deg[col[e]] += ew[e]
__global__ void deg_kernel(const int* __restrict__ col, const float* __restrict__ ew, int E)
{
    int e = blockIdx.x * blockDim.x + threadIdx.x;
    if (e < E) atomicAdd(&g_deg[col[e]], ew[e]);
}

// deg -> deg^{-1/2} (0 where deg<=0), in place
__global__ void dis_kernel(int N)
{
    int n = blockIdx.x * blockDim.x + threadIdx.x;
    if (n < N) {
        float d = g_deg[n];
        g_deg[n] = (d > 0.0f) ? rsqrtf(d) : 0.0f;
    }
}

// norm[e] = dis[row]*ew*dis[col]
__global__ void norm_kernel(const int* __restrict__ row, const int* __restrict__ col,
                            const float* __restrict__ ew, int E)
{
    int e = blockIdx.x * blockDim.x + threadIdx.x;
    if (e < E) g_norm[e] = g_deg[row[e]] * ew[e] * g_deg[col[e]];
}

// tgt[col[e], :] += norm[e] * h[row[e], :]
// 8 threads per edge, each owns 4 contiguous floats; vector red cuts atomic count 4x.
__global__ void scatter_kernel(float* __restrict__ tgt, const float* __restrict__ h,
                               const int* __restrict__ row, const int* __restrict__ col,
                               int E)
{
    unsigned idx = blockIdx.x * blockDim.x + threadIdx.x;
    unsigned e = idx >> 3;
    unsigned q = idx & 7u;
    if (e >= (unsigned)E) return;
    int r = row[e];
    int c = col[e];
    float w = g_norm[e];
    float4 v = *reinterpret_cast<const float4*>(h + (size_t)r * D + q * 4);
    v.x *= w; v.y *= w; v.z *= w; v.w *= w;
    float* p = tgt + (size_t)c * D + q * 4;
    asm volatile("red.global.add.v4.f32 [%0], {%1, %2, %3, %4};"
                 :: "l"(p), "f"(v.x), "f"(v.y), "f"(v.z), "f"(v.w)
                 : "memory");
}

// out[n,:] (op)= h[n,:] @ W   with W a 32x32 row-major block.
// mode 0: out = h@W            (INIT)
// mode 1: out += h@W           (ACCUM)
// mode 2: dst = relu(out + h@W + bias)   (FINAL; out itself not written)
__global__ void gemm_kernel(float* __restrict__ out, const float* __restrict__ h,
                            const float* __restrict__ W, int mode,
                            const float* __restrict__ bias, float* __restrict__ dst,
                            int N)
{
    int lane = threadIdx.x & 31;
    int warp = (blockIdx.x * blockDim.x + threadIdx.x) >> 5;
    int nwarps = (gridDim.x * blockDim.x) >> 5;

    // lane j holds column j of W: Wreg[i] = W[i][j]
    float Wreg[D];
#pragma unroll
    for (int i = 0; i < D; i++) Wreg[i] = W[i * D + lane];
    float bv = (mode == 2) ? bias[lane] : 0.0f;

    for (int n = warp; n < N; n += nwarps) {
        float hv = h[(size_t)n * D + lane];
        float acc = 0.0f;
#pragma unroll
        for (int i = 0; i < D; i++)
            acc = fmaf(__shfl_sync(0xffffffffu, hv, i), Wreg[i], acc);

        size_t o = (size_t)n * D + lane;
        if (mode == 0) {
            out[o] = acc;
        } else if (mode == 1) {
            out[o] += acc;
        } else {
            float v = out[o] + acc + bv;
            dst[o] = fmaxf(v, 0.0f);
        }
    }
}

// ---------------- launch ----------------

extern "C" void kernel_launch(void* const* d_in, const int* in_sizes, int n_in,
                              void* d_out, int out_size)
{
    const float* x  = (const float*)d_in[0];
    const int*   ei = (const int*)d_in[1];
    const float* ew = (const float*)d_in[2];
    const float* W  = (const float*)d_in[3];
    const float* b  = (const float*)d_in[4];

    const int N = in_sizes[0] / D;
    const int E = in_sizes[2];

    const int* row = ei;       // edge_index[0]
    const int* col = ei + E;   // edge_index[1]

    float* deg_p;  cudaGetSymbolAddress((void**)&deg_p,  g_deg);
    float* h1_p;   cudaGetSymbolAddress((void**)&h1_p,   g_h1);
    float* h2_p;   cudaGetSymbolAddress((void**)&h2_p,   g_h2);
    float* out_p;  cudaGetSymbolAddress((void**)&out_p,  g_out);
    float* x_p;    cudaGetSymbolAddress((void**)&x_p,    g_x);

    const int TB = 256;

    // ---- norm precompute ----
    cudaMemsetAsync(deg_p, 0, (size_t)N * sizeof(float));
    deg_kernel<<<(E + TB - 1) / TB, TB>>>(col, ew, E);
    dis_kernel<<<(N + TB - 1) / TB, TB>>>(N);
    norm_kernel<<<(E + TB - 1) / TB, TB>>>(row, col, ew, E);

    const int gemm_blocks = 1184;                 // ~9.5k warps, grid-stride over nodes
    const int scat_blocks = (E * 8 + TB - 1) / TB;

    const float* xcur = x;
    for (int l = 0; l < LAYERS; l++) {
        // out = x @ W[l,0]
        gemm_kernel<<<gemm_blocks, TB>>>(out_p, xcur, W + (size_t)(l * (HOPS + 1)) * D * D,
                                         0, nullptr, nullptr, N);
        const float* hprev = xcur;
        for (int k = 1; k <= HOPS; k++) {
            float* tgt = (k & 1) ? h1_p : h2_p;
            cudaMemsetAsync(tgt, 0, (size_t)N * D * sizeof(float));
            scatter_kernel<<<scat_blocks, TB>>>(tgt, hprev, row, col, E);

            int mode = (k == HOPS) ? 2 : 1;
            float* dst = (l == LAYERS - 1) ? (float*)d_out : x_p;
            gemm_kernel<<<gemm_blocks, TB>>>(out_p, tgt,
                                             W + (size_t)(l * (HOPS + 1) + k) * D * D,
                                             mode, b + (size_t)l * D, dst, N);
            hprev = tgt;
        }
        xcur = x_p;
    }
}

// round 3
// speedup vs baseline: 1.1103x; 1.1103x over previous
#include <cuda_runtime.h>
#include <cuda_bf16.h>
#include <cstdint>

#define NODES 100000
#define EDGES 1600000
#define D 32
#define LAYERS 3
#define HOPS 3

#define SCAN_B 512

// ---------------- scratch (device globals) ----------------
__device__ float g_dis[NODES];                    // deg -> deg^{-1/2}
__device__ int   g_count[NODES];
__device__ int   g_fill[NODES];
__device__ int   g_rowptr[NODES + 1];
__device__ int   g_bsum[1024];
__device__ __align__(16) int2 g_epack[EDGES];     // (row, __float_as_int(norm)) grouped by col
__device__ float g_bufS[NODES * D];
__device__ float g_bufG[NODES * D];
__device__ float g_x[NODES * D];

// ---------------- setup kernels ----------------

__global__ void deg_kernel(const int* __restrict__ col, const float* __restrict__ ew, int E)
{
    int e = blockIdx.x * blockDim.x + threadIdx.x;
    if (e < E) {
        int c = col[e];
        atomicAdd(&g_dis[c], ew[e]);
        atomicAdd(&g_count[c], 1);
    }
}

__global__ void dis_kernel(int N)
{
    int n = blockIdx.x * blockDim.x + threadIdx.x;
    if (n < N) {
        float d = g_dis[n];
        g_dis[n] = (d > 0.0f) ? rsqrtf(d) : 0.0f;
    }
}

// block-level exclusive scan of g_count -> g_rowptr (partial), block totals -> g_bsum
__global__ void scan1_kernel(int N)
{
    __shared__ int sh[SCAN_B];
    int t = threadIdx.x;
    int i = blockIdx.x * SCAN_B + t;
    int v = (i < N) ? g_count[i] : 0;
    sh[t] = v;
    __syncthreads();
#pragma unroll
    for (int off = 1; off < SCAN_B; off <<= 1) {
        int add = (t >= off) ? sh[t - off] : 0;
        __syncthreads();
        sh[t] += add;
        __syncthreads();
    }
    int incl = sh[t];
    if (i < N) g_rowptr[i] = incl - v;  // exclusive within block
    if (t == SCAN_B - 1) g_bsum[blockIdx.x] = incl;
}

__global__ void scan2_kernel(int nb)
{
    if (threadIdx.x == 0 && blockIdx.x == 0) {
        int run = 0;
        for (int j = 0; j < nb; j++) { int v = g_bsum[j]; g_bsum[j] = run; run += v; }
    }
}

__global__ void scan3_kernel(int N, int E)
{
    int i = blockIdx.x * blockDim.x + threadIdx.x;
    if (i < N) g_rowptr[i] += g_bsum[i / SCAN_B];
    if (i == 0) g_rowptr[N] = E;
}

// scatter edges into CSR slots grouped by col; fuse norm computation
__global__ void fill_kernel(const int* __restrict__ row, const int* __restrict__ col,
                            const float* __restrict__ ew, int E)
{
    int e = blockIdx.x * blockDim.x + threadIdx.x;
    if (e < E) {
        int r = row[e];
        int c = col[e];
        float w = g_dis[r] * ew[e] * g_dis[c];
        int p = g_rowptr[c] + atomicAdd(&g_fill[c], 1);
        g_epack[p] = make_int2(r, __float_as_int(w));
    }
}

// ---------------- hop: dst[n,:] = sum_{e in csr(n)} norm_e * h[row_e, :]  (warp per node)
__global__ void gather_kernel(float* __restrict__ dst, const float* __restrict__ h, int N)
{
    int gt = blockIdx.x * blockDim.x + threadIdx.x;
    int n = gt >> 5;
    int lane = gt & 31;
    if (n >= N) return;

    int s = g_rowptr[n];
    int e = g_rowptr[n + 1];
    float acc = 0.0f;

    int i = s;
    if ((i & 1) && i < e) {               // align to even for int4 pair loads
        int2 t = g_epack[i];
        acc = fmaf(__int_as_float(t.y), h[(size_t)t.x * D + lane], acc);
        i++;
    }
    for (; i + 2 <= e; i += 2) {
        int4 t = *reinterpret_cast<const int4*>(&g_epack[i]);
        float v0 = h[(size_t)t.x * D + lane];
        float v1 = h[(size_t)t.z * D + lane];
        acc = fmaf(__int_as_float(t.y), v0, acc);
        acc = fmaf(__int_as_float(t.w), v1, acc);
    }
    if (i < e) {
        int2 t = g_epack[i];
        acc = fmaf(__int_as_float(t.y), h[(size_t)t.x * D + lane], acc);
    }
    dst[(size_t)n * D + lane] = acc;
}

// ---------------- GEMM: thread per node, W in smem, acc[32] in regs ----------------
// mode 0: dst = x@W
// mode 1: dst = x@W + add
// mode 2: dst = relu(x@W + add + bias)
__global__ __launch_bounds__(256)
void gemm_kernel(float* __restrict__ dst, const float* __restrict__ x,
                 const float* __restrict__ W, const float* __restrict__ add,
                 const float* __restrict__ bias, int mode, int N)
{
    __shared__ float Ws[D * D];
    __shared__ float Bs[D];
    int t = threadIdx.x;
    reinterpret_cast<float4*>(Ws)[t] = reinterpret_cast<const float4*>(W)[t];
    if (t < D) Bs[t] = (mode == 2) ? bias[t] : 0.0f;
    __syncthreads();

    int n = blockIdx.x * 256 + t;
    if (n >= N) return;

    float h[D];
    const float4* xr = reinterpret_cast<const float4*>(x + (size_t)n * D);
#pragma unroll
    for (int q = 0; q < 8; q++) {
        float4 v = xr[q];
        h[q * 4] = v.x; h[q * 4 + 1] = v.y; h[q * 4 + 2] = v.z; h[q * 4 + 3] = v.w;
    }

    float acc[D];
#pragma unroll
    for (int j = 0; j < D; j++) acc[j] = 0.0f;

#pragma unroll
    for (int i = 0; i < D; i++) {
        float hv = h[i];
        const float4* wr = reinterpret_cast<const float4*>(Ws + i * D);
#pragma unroll
        for (int q = 0; q < 8; q++) {
            float4 wv = wr[q];
            acc[q * 4]     = fmaf(hv, wv.x, acc[q * 4]);
            acc[q * 4 + 1] = fmaf(hv, wv.y, acc[q * 4 + 1]);
            acc[q * 4 + 2] = fmaf(hv, wv.z, acc[q * 4 + 2]);
            acc[q * 4 + 3] = fmaf(hv, wv.w, acc[q * 4 + 3]);
        }
    }

    float* drow = dst + (size_t)n * D;
    if (mode == 0) {
#pragma unroll
        for (int q = 0; q < 8; q++)
            reinterpret_cast<float4*>(drow)[q] =
                make_float4(acc[q*4], acc[q*4+1], acc[q*4+2], acc[q*4+3]);
    } else if (mode == 1) {
        const float4* ar = reinterpret_cast<const float4*>(add + (size_t)n * D);
#pragma unroll
        for (int q = 0; q < 8; q++) {
            float4 a = ar[q];
            reinterpret_cast<float4*>(drow)[q] =
                make_float4(acc[q*4] + a.x, acc[q*4+1] + a.y,
                            acc[q*4+2] + a.z, acc[q*4+3] + a.w);
        }
    } else {
        const float4* ar = reinterpret_cast<const float4*>(add + (size_t)n * D);
#pragma unroll
        for (int q = 0; q < 8; q++) {
            float4 a = ar[q];
            float4 o;
            o.x = fmaxf(acc[q*4]     + a.x + Bs[q*4],     0.0f);
            o.y = fmaxf(acc[q*4 + 1] + a.y + Bs[q*4 + 1], 0.0f);
            o.z = fmaxf(acc[q*4 + 2] + a.z + Bs[q*4 + 2], 0.0f);
            o.w = fmaxf(acc[q*4 + 3] + a.w + Bs[q*4 + 3], 0.0f);
            reinterpret_cast<float4*>(drow)[q] = o;
        }
    }
}

// ---------------- launch ----------------

extern "C" void kernel_launch(void* const* d_in, const int* in_sizes, int n_in,
                              void* d_out, int out_size)
{
    const float* x  = (const float*)d_in[0];
    const int*   ei = (const int*)d_in[1];
    const float* ew = (const float*)d_in[2];
    const float* W  = (const float*)d_in[3];
    const float* b  = (const float*)d_in[4];

    const int N = in_sizes[0] / D;
    const int E = in_sizes[2];

    const int* row = ei;
    const int* col = ei + E;

    float* dis_p;   cudaGetSymbolAddress((void**)&dis_p,   g_dis);
    int*   cnt_p;   cudaGetSymbolAddress((void**)&cnt_p,   g_count);
    int*   fill_p;  cudaGetSymbolAddress((void**)&fill_p,  g_fill);
    float* bufS_p;  cudaGetSymbolAddress((void**)&bufS_p,  g_bufS);
    float* bufG_p;  cudaGetSymbolAddress((void**)&bufG_p,  g_bufG);
    float* x_p;     cudaGetSymbolAddress((void**)&x_p,     g_x);

    const int TB = 256;
    const int eb = (E + TB - 1) / TB;
    const int nb = (N + TB - 1) / TB;
    const int scan_blocks = (N + SCAN_B - 1) / SCAN_B;

    // ---- CSR + norm build ----
    cudaMemsetAsync(dis_p,  0, (size_t)N * sizeof(float));
    cudaMemsetAsync(cnt_p,  0, (size_t)N * sizeof(int));
    cudaMemsetAsync(fill_p, 0, (size_t)N * sizeof(int));
    deg_kernel<<<eb, TB>>>(col, ew, E);
    dis_kernel<<<nb, TB>>>(N);
    scan1_kernel<<<scan_blocks, SCAN_B>>>(N);
    scan2_kernel<<<1, 32>>>(scan_blocks);
    scan3_kernel<<<nb, TB>>>(N, E);
    fill_kernel<<<eb, TB>>>(row, col, ew, E);

    const int gemm_blocks   = (N + 255) / 256;
    const int gather_blocks = (N * 32 + TB - 1) / TB;

    const float* xcur = x;
    for (int l = 0; l < LAYERS; l++) {
        const float* Wl = W + (size_t)l * (HOPS + 1) * D * D;
        // Horner: out = xW0 + A(xW1 + A(xW2 + A(xW3)))
        gemm_kernel<<<gemm_blocks, 256>>>(bufS_p, xcur, Wl + 3 * D * D, nullptr, nullptr, 0, N);
        gather_kernel<<<gather_blocks, TB>>>(bufG_p, bufS_p, N);
        gemm_kernel<<<gemm_blocks, 256>>>(bufS_p, xcur, Wl + 2 * D * D, bufG_p, nullptr, 1, N);
        gather_kernel<<<gather_blocks, TB>>>(bufG_p, bufS_p, N);
        gemm_kernel<<<gemm_blocks, 256>>>(bufS_p, xcur, Wl + 1 * D * D, bufG_p, nullptr, 1, N);
        gather_kernel<<<gather_blocks, TB>>>(bufG_p, bufS_p, N);

        float* dst = (l == LAYERS - 1) ? (float*)d_out : x_p;
        gemm_kernel<<<gemm_blocks, 256>>>(dst, xcur, Wl, bufG_p, b + (size_t)l * D, 2, N);
        xcur = x_p;
    }
}

// round 4
// speedup vs baseline: 1.2941x; 1.1655x over previous
#include <cuda_runtime.h>
#include <cuda_bf16.h>
#include <cstdint>

#define NODES 100000
#define EDGES 1600000
#define D 32
#define LAYERS 3
#define HOPS 3

#define SCAN_B 512

// ---------------- scratch (device globals) ----------------
__device__ float g_tmp3[NODES * 3];               // [dis | count | fill] zeroed with ONE memset
__device__ int   g_rowptr[NODES + 1];
__device__ int   g_bsum[256];
__device__ __align__(16) int2 g_epack[EDGES];     // (row, __float_as_int(norm)) grouped by col
__device__ float g_P[4 * NODES * D];              // P_k = x @ W[l,k]
__device__ float g_bufS[NODES * D];
__device__ float g_bufG[NODES * D];
__device__ float g_x[NODES * D];

// ---------------- f32x2 helpers ----------------
__device__ __forceinline__ unsigned long long pack2(float a, float b) {
    unsigned long long r;
    asm("mov.b64 %0, {%1, %2};" : "=l"(r) : "f"(a), "f"(b));
    return r;
}
__device__ __forceinline__ float2 unpack2(unsigned long long v) {
    float2 r;
    asm("mov.b64 {%0, %1}, %2;" : "=f"(r.x), "=f"(r.y) : "l"(v));
    return r;
}
__device__ __forceinline__ void fma2(unsigned long long& d,
                                     unsigned long long a, unsigned long long b) {
    asm("fma.rn.f32x2 %0, %1, %2, %0;" : "+l"(d) : "l"(a), "l"(b));
}

// ---------------- setup kernels ----------------

__global__ void deg_kernel(const int* __restrict__ col, const float* __restrict__ ew, int E)
{
    int e = blockIdx.x * blockDim.x + threadIdx.x;
    if (e < E) {
        int c = col[e];
        atomicAdd(&g_tmp3[c], ew[e]);                                  // deg
        atomicAdd(reinterpret_cast<int*>(g_tmp3 + NODES) + c, 1);      // count
    }
}

// block-level exclusive scan of count -> g_rowptr (partial), block totals -> g_bsum
__global__ void scan1_kernel(int N)
{
    __shared__ int sh[SCAN_B];
    const int* cnt = reinterpret_cast<const int*>(g_tmp3 + NODES);
    int t = threadIdx.x;
    int i = blockIdx.x * SCAN_B + t;
    int v = (i < N) ? cnt[i] : 0;
    sh[t] = v;
    __syncthreads();
#pragma unroll
    for (int off = 1; off < SCAN_B; off <<= 1) {
        int add = (t >= off) ? sh[t - off] : 0;
        __syncthreads();
        sh[t] += add;
        __syncthreads();
    }
    int incl = sh[t];
    if (i < N) g_rowptr[i] = incl - v;
    if (t == SCAN_B - 1) g_bsum[blockIdx.x] = incl;
}

// parallel exclusive scan of the (<=256) block sums
__global__ void scan2_kernel(int nb)
{
    __shared__ int sh[256];
    int t = threadIdx.x;
    int v = (t < nb) ? g_bsum[t] : 0;
    sh[t] = v;
    __syncthreads();
#pragma unroll
    for (int off = 1; off < 256; off <<= 1) {
        int add = (t >= off) ? sh[t - off] : 0;
        __syncthreads();
        sh[t] += add;
        __syncthreads();
    }
    if (t < nb) g_bsum[t] = sh[t] - v;
}

// rowptr += block offset; also deg -> deg^{-1/2}
__global__ void scan3_kernel(int N, int E)
{
    int i = blockIdx.x * blockDim.x + threadIdx.x;
    if (i < N) {
        g_rowptr[i] += g_bsum[i / SCAN_B];
        float d = g_tmp3[i];
        g_tmp3[i] = (d > 0.0f) ? rsqrtf(d) : 0.0f;
    }
    if (i == 0) g_rowptr[N] = E;
}

// scatter edges into CSR slots grouped by col; fuse norm computation
__global__ void fill_kernel(const int* __restrict__ row, const int* __restrict__ col,
                            const float* __restrict__ ew, int E)
{
    int* fill = reinterpret_cast<int*>(g_tmp3 + 2 * NODES);
    int e = blockIdx.x * blockDim.x + threadIdx.x;
    if (e < E) {
        int r = row[e];
        int c = col[e];
        float w = g_tmp3[r] * ew[e] * g_tmp3[c];
        int p = g_rowptr[c] + atomicAdd(&fill[c], 1);
        g_epack[p] = make_int2(r, __float_as_int(w));
    }
}

// ---------------- multigemm: P[k][n,:] = x[n,:] @ W4[k]  for k=0..3 ----------------
__global__ __launch_bounds__(256)
void multigemm_kernel(float* __restrict__ P, const float* __restrict__ x,
                      const float* __restrict__ W4, int N)
{
    __shared__ float Ws[4 * D * D];   // 16 KB
    int t = threadIdx.x;
#pragma unroll
    for (int q = 0; q < 4; q++)
        reinterpret_cast<float4*>(Ws)[q * 256 + t] =
            reinterpret_cast<const float4*>(W4)[q * 256 + t];
    __syncthreads();

    int n = blockIdx.x * 256 + t;
    if (n >= N) return;

    float h[D];
    const float4* xr = reinterpret_cast<const float4*>(x + (size_t)n * D);
#pragma unroll
    for (int q = 0; q < 8; q++) {
        float4 v = xr[q];
        h[q * 4] = v.x; h[q * 4 + 1] = v.y; h[q * 4 + 2] = v.z; h[q * 4 + 3] = v.w;
    }

#pragma unroll
    for (int k = 0; k < 4; k++) {
        unsigned long long acc[D / 2];
#pragma unroll
        for (int j = 0; j < D / 2; j++) acc[j] = 0ull;

        const unsigned long long* Wk =
            reinterpret_cast<const unsigned long long*>(Ws + k * D * D);
#pragma unroll
        for (int i = 0; i < D; i++) {
            unsigned long long hv2 = pack2(h[i], h[i]);
            const unsigned long long* wr = Wk + i * (D / 2);
#pragma unroll
            for (int j = 0; j < D / 2; j++)
                fma2(acc[j], hv2, wr[j]);
        }

        float* drow = P + (size_t)k * N * D + (size_t)n * D;
#pragma unroll
        for (int j2 = 0; j2 < D / 4; j2++) {
            float2 a = unpack2(acc[j2 * 2]);
            float2 b = unpack2(acc[j2 * 2 + 1]);
            reinterpret_cast<float4*>(drow)[j2] = make_float4(a.x, a.y, b.x, b.y);
        }
    }
}

// ---------------- fused hop: dst[n,:] = P[n,:] + sum_e norm_e * h[row_e,:]
// mode 0: plain;  mode 1: + bias then ReLU
__global__ void gather_kernel(float* __restrict__ dst, const float* __restrict__ h,
                              const float* __restrict__ P, const float* __restrict__ bias,
                              int mode, int N)
{
    int gt = blockIdx.x * blockDim.x + threadIdx.x;
    int n = gt >> 5;
    int lane = gt & 31;
    if (n >= N) return;

    int s = g_rowptr[n];
    int e = g_rowptr[n + 1];
    float acc = 0.0f;

    int i = s;
    if ((i & 1) && i < e) {
        int2 t = g_epack[i];
        acc = fmaf(__int_as_float(t.y), h[(size_t)t.x * D + lane], acc);
        i++;
    }
    int npair = (e - i) >> 1;
    const int4* pp = reinterpret_cast<const int4*>(g_epack + i);
#pragma unroll 2
    for (int p = 0; p < npair; p++) {
        int4 t = pp[p];
        float v0 = h[(size_t)t.x * D + lane];
        float v1 = h[(size_t)t.z * D + lane];
        acc = fmaf(__int_as_float(t.y), v0, acc);
        acc = fmaf(__int_as_float(t.w), v1, acc);
    }
    i += npair * 2;
    if (i < e) {
        int2 t = g_epack[i];
        acc = fmaf(__int_as_float(t.y), h[(size_t)t.x * D + lane], acc);
    }

    float v = P[(size_t)n * D + lane] + acc;
    if (mode == 1) v = fmaxf(v + bias[lane], 0.0f);
    dst[(size_t)n * D + lane] = v;
}

// ---------------- launch ----------------

extern "C" void kernel_launch(void* const* d_in, const int* in_sizes, int n_in,
                              void* d_out, int out_size)
{
    const float* x  = (const float*)d_in[0];
    const int*   ei = (const int*)d_in[1];
    const float* ew = (const float*)d_in[2];
    const float* W  = (const float*)d_in[3];
    const float* b  = (const float*)d_in[4];

    const int N = in_sizes[0] / D;
    const int E = in_sizes[2];

    const int* row = ei;
    const int* col = ei + E;

    float* tmp3_p;  cudaGetSymbolAddress((void**)&tmp3_p,  g_tmp3);
    float* P_p;     cudaGetSymbolAddress((void**)&P_p,     g_P);
    float* bufS_p;  cudaGetSymbolAddress((void**)&bufS_p,  g_bufS);
    float* bufG_p;  cudaGetSymbolAddress((void**)&bufG_p,  g_bufG);
    float* x_p;     cudaGetSymbolAddress((void**)&x_p,     g_x);

    const int TB = 256;
    const int eb = (E + TB - 1) / TB;
    const int nb = (N + TB - 1) / TB;
    const int scan_blocks = (N + SCAN_B - 1) / SCAN_B;

    // ---- CSR + norm build ----
    cudaMemsetAsync(tmp3_p, 0, (size_t)3 * N * sizeof(float));
    deg_kernel<<<eb, TB>>>(col, ew, E);
    scan1_kernel<<<scan_blocks, SCAN_B>>>(N);
    scan2_kernel<<<1, 256>>>(scan_blocks);
    scan3_kernel<<<nb, TB>>>(N, E);
    fill_kernel<<<eb, TB>>>(row, col, ew, E);

    const int mg_blocks     = (N + 255) / 256;
    const int gather_blocks = (N * 32 + TB - 1) / TB;
    const size_t ND = (size_t)N * D;

    const float* xcur = x;
    for (int l = 0; l < LAYERS; l++) {
        const float* Wl = W + (size_t)l * (HOPS + 1) * D * D;
        multigemm_kernel<<<mg_blocks, 256>>>(P_p, xcur, Wl, N);

        // Horner: x' = relu(P0 + A(P1 + A(P2 + A*P3)) + b)
        gather_kernel<<<gather_blocks, TB>>>(bufS_p, P_p + 3 * ND, P_p + 2 * ND,
                                             nullptr, 0, N);
        gather_kernel<<<gather_blocks, TB>>>(bufG_p, bufS_p, P_p + 1 * ND,
                                             nullptr, 0, N);
        float* dst = (l == LAYERS - 1) ? (float*)d_out : x_p;
        gather_kernel<<<gather_blocks, TB>>>(dst, bufG_p, P_p,
                                             b + (size_t)l * D, 1, N);
        xcur = x_p;
    }
}